// round 2
// baseline (speedup 1.0000x reference)
#include <cuda_runtime.h>
#include <math.h>

#define NN   100000
#define EE   1600000
#define FIN  512
#define HIDN 64
#define CO   16

#define SCAN_B 512
#define NBLK  ((NN + SCAN_B - 1) / SCAN_B)   // 196

// ---------------- scratch (device globals; no allocations allowed) ----------
__device__ int   g_degi[NN];          // in-degree (int)
__device__ int   g_cnt [NN];          // placement counters
__device__ int   g_rs  [NN];          // CSR row start (exclusive scan of degi)
__device__ int   g_bsum [256];
__device__ int   g_bsumx[256];
__device__ float g_dis [NN];          // deg^-1/2 (with self loop)
__device__ int   g_esrc[EE];          // CSR: src per slot (sorted by dst)
__device__ float g_ew  [EE];          // CSR: edge weight dis[src]*dis[dst]
__device__ float g_h1  [(size_t)NN * HIDN];
__device__ float g_h2  [(size_t)NN * CO];
__device__ int   g_is64;

// ---------------- edge index dtype detection --------------------------------
// int64 storage => high word of each entry is 0 (indices < 100000).
// int32 storage => odd words are random indices, ~never all zero in 64 samples.
__global__ void k_detect(const unsigned* __restrict__ w) {
    if (threadIdx.x == 0) {
        int is64 = 1;
        #pragma unroll 1
        for (int i = 1; i < 128; i += 2)
            if (w[i] != 0u) { is64 = 0; break; }
        g_is64 = is64;
    }
}

__device__ __forceinline__ int eidx(const void* edge, int is64, long long p) {
    return is64 ? (int)__ldg(((const long long*)edge) + p)
                : __ldg(((const int*)edge) + p);
}

// ---------------- per-launch init -------------------------------------------
__global__ void k_zero() {
    int i = blockIdx.x * blockDim.x + threadIdx.x;
    if (i < NN) { g_degi[i] = 0; g_cnt[i] = 0; }
}

__global__ void k_deg(const void* __restrict__ edge) {
    int e = blockIdx.x * blockDim.x + threadIdx.x;
    if (e >= EE) return;
    int dst = eidx(edge, g_is64, (long long)EE + e);
    atomicAdd(&g_degi[dst], 1);
}

__global__ void k_dis() {
    int i = blockIdx.x * blockDim.x + threadIdx.x;
    if (i < NN) g_dis[i] = rsqrtf((float)g_degi[i] + 1.0f);
}

// ---------------- exclusive scan of g_degi -> g_rs (2-level) ----------------
__global__ void k_scan1() {
    __shared__ int s[SCAN_B];
    int t = threadIdx.x, b = blockIdx.x, i = b * SCAN_B + t;
    int v = (i < NN) ? g_degi[i] : 0;
    s[t] = v; __syncthreads();
    for (int off = 1; off < SCAN_B; off <<= 1) {
        int xv = (t >= off) ? s[t - off] : 0;
        __syncthreads();
        s[t] += xv;
        __syncthreads();
    }
    if (i < NN) g_rs[i] = s[t] - v;
    if (t == SCAN_B - 1) g_bsum[b] = s[t];
}

__global__ void k_scan2() {
    __shared__ int s[256];
    int t = threadIdx.x;
    int v = (t < NBLK) ? g_bsum[t] : 0;
    s[t] = v; __syncthreads();
    for (int off = 1; off < 256; off <<= 1) {
        int xv = (t >= off) ? s[t - off] : 0;
        __syncthreads();
        s[t] += xv;
        __syncthreads();
    }
    g_bsumx[t] = s[t] - v;
}

__global__ void k_scan3() {
    int i = blockIdx.x * blockDim.x + threadIdx.x;
    if (i < NN) g_rs[i] += g_bsumx[i / SCAN_B];
}

// ---------------- counting-sort placement (CSR build) -----------------------
__global__ void k_build(const void* __restrict__ edge) {
    int e = blockIdx.x * blockDim.x + threadIdx.x;
    if (e >= EE) return;
    int is64 = g_is64;
    int src = eidx(edge, is64, e);
    int dst = eidx(edge, is64, (long long)EE + e);
    int pos = g_rs[dst] + atomicAdd(&g_cnt[dst], 1);
    g_esrc[pos] = src;
    g_ew[pos]   = g_dis[src] * g_dis[dst];
}

// ---------------- GEMM1: h1 = x @ W1   (N x 512) @ (512 x 64) ---------------
__global__ __launch_bounds__(256) void k_gemm1(const float* __restrict__ x,
                                               const float* __restrict__ W1) {
    __shared__ float As[16][64];   // [k][row]
    __shared__ float Bs[16][64];   // [k][col]
    int tid = threadIdx.x;
    int tx = tid & 15, ty = tid >> 4;
    int rowBase = blockIdx.x * 64;

    float acc[4][4] = {};

    for (int k0 = 0; k0 < FIN; k0 += 16) {
        #pragma unroll
        for (int l = 0; l < 4; l++) {
            int idx = tid + l * 256;
            int r = idx >> 4, c = idx & 15;
            int gr = rowBase + r;
            As[c][r] = (gr < NN) ? x[(size_t)gr * FIN + k0 + c] : 0.0f;
        }
        #pragma unroll
        for (int l = 0; l < 4; l++) {
            int idx = tid + l * 256;
            int r = idx >> 6, c = idx & 63;
            Bs[r][c] = W1[(k0 + r) * HIDN + c];
        }
        __syncthreads();

        #pragma unroll
        for (int k = 0; k < 16; k++) {
            float4 a = *(const float4*)&As[k][ty * 4];
            float4 b = *(const float4*)&Bs[k][tx * 4];
            float av[4] = {a.x, a.y, a.z, a.w};
            float bv[4] = {b.x, b.y, b.z, b.w};
            #pragma unroll
            for (int i = 0; i < 4; i++)
                #pragma unroll
                for (int j = 0; j < 4; j++)
                    acc[i][j] += av[i] * bv[j];
        }
        __syncthreads();
    }

    #pragma unroll
    for (int i = 0; i < 4; i++) {
        int r = rowBase + ty * 4 + i;
        if (r < NN)
            *(float4*)&g_h1[(size_t)r * HIDN + tx * 4] =
                make_float4(acc[i][0], acc[i][1], acc[i][2], acc[i][3]);
    }
}

// ---------------- gather layer 1 (fused relu + bias + self-loop + GEMM2) ----
// warp per node: 64 cols as 2 per lane; then 16-col GEMM with W2 in smem.
__global__ __launch_bounds__(256) void k_gather1(const float* __restrict__ b1,
                                                 const float* __restrict__ W2) {
    __shared__ float W2s[HIDN * CO];
    __shared__ float b1s[HIDN];
    __shared__ float hs[8][HIDN];
    for (int i = threadIdx.x; i < HIDN * CO; i += 256) W2s[i] = W2[i];
    if (threadIdx.x < HIDN) b1s[threadIdx.x] = b1[threadIdx.x];
    __syncthreads();

    int warp = threadIdx.x >> 5, lane = threadIdx.x & 31;
    int n = blockIdx.x * 8 + warp;
    if (n >= NN) return;

    float acc0 = 0.0f, acc1 = 0.0f;
    int beg = g_rs[n], end = beg + g_degi[n];

    int e = beg;
    for (; e + 1 < end; e += 2) {
        int   s0 = g_esrc[e],   s1 = g_esrc[e + 1];
        float w0 = g_ew[e],     w1 = g_ew[e + 1];
        float2 v0 = *(const float2*)&g_h1[(size_t)s0 * HIDN + lane * 2];
        float2 v1 = *(const float2*)&g_h1[(size_t)s1 * HIDN + lane * 2];
        acc0 += w0 * v0.x + w1 * v1.x;
        acc1 += w0 * v0.y + w1 * v1.y;
    }
    if (e < end) {
        int s0 = g_esrc[e]; float w0 = g_ew[e];
        float2 v0 = *(const float2*)&g_h1[(size_t)s0 * HIDN + lane * 2];
        acc0 += w0 * v0.x;
        acc1 += w0 * v0.y;
    }

    float dd = g_dis[n]; dd *= dd;
    float2 hv = *(const float2*)&g_h1[(size_t)n * HIDN + lane * 2];
    acc0 = fmaxf(acc0 + dd * hv.x + b1s[lane * 2 + 0], 0.0f);
    acc1 = fmaxf(acc1 + dd * hv.y + b1s[lane * 2 + 1], 0.0f);
    hs[warp][lane * 2 + 0] = acc0;
    hs[warp][lane * 2 + 1] = acc1;
    __syncwarp();

    // h2[n, c] = sum_k relu_h[k] * W2[k, c]; lanes split k-range in halves.
    int c = lane & 15, half = lane >> 4;
    float s = 0.0f;
    #pragma unroll
    for (int k = half * 32; k < half * 32 + 32; k++)
        s += hs[warp][k] * W2s[k * CO + c];
    s += __shfl_down_sync(0xffffffffu, s, 16);
    if (half == 0) g_h2[(size_t)n * CO + c] = s;
}

// ---------------- gather layer 2 (fused bias + self-loop + log_softmax) -----
__global__ __launch_bounds__(256) void k_gather2(const float* __restrict__ b2,
                                                 float* __restrict__ out) {
    int warp = threadIdx.x >> 5, lane = threadIdx.x & 31;
    int n = blockIdx.x * 8 + warp;
    if (n >= NN) return;
    int c = lane & 15, half = lane >> 4;

    float acc = 0.0f;
    int beg = g_rs[n], end = beg + g_degi[n];
    for (int e = beg + half; e < end; e += 2)
        acc += g_ew[e] * g_h2[(size_t)g_esrc[e] * CO + c];
    acc += __shfl_xor_sync(0xffffffffu, acc, 16);

    float dd = g_dis[n]; dd *= dd;
    float z = acc + dd * g_h2[(size_t)n * CO + c] + __ldg(&b2[c]);

    float m = z;
    #pragma unroll
    for (int off = 8; off; off >>= 1)
        m = fmaxf(m, __shfl_xor_sync(0xffffffffu, m, off));
    float sum = expf(z - m);
    #pragma unroll
    for (int off = 8; off; off >>= 1)
        sum += __shfl_xor_sync(0xffffffffu, sum, off);
    float l = m + logf(sum);

    if (half == 0) out[(size_t)n * CO + c] = z - l;
}

// ---------------- launch -----------------------------------------------------
extern "C" void kernel_launch(void* const* d_in, const int* in_sizes, int n_in,
                              void* d_out, int out_size) {
    const float* x    = (const float*)d_in[0];
    const void*  edge = d_in[1];
    const float* W1   = (const float*)d_in[2];
    const float* b1   = (const float*)d_in[3];
    const float* W2   = (const float*)d_in[4];
    const float* b2   = (const float*)d_in[5];
    float* out = (float*)d_out;

    k_detect<<<1, 32>>>((const unsigned*)edge);
    k_zero<<<(NN + 255) / 256, 256>>>();
    k_deg<<<(EE + 255) / 256, 256>>>(edge);
    k_dis<<<(NN + 255) / 256, 256>>>();
    k_scan1<<<NBLK, SCAN_B>>>();
    k_scan2<<<1, 256>>>();
    k_scan3<<<(NN + 255) / 256, 256>>>();
    k_build<<<(EE + 255) / 256, 256>>>(edge);
    k_gemm1<<<(NN + 63) / 64, 256>>>(x, W1);
    k_gather1<<<(NN + 7) / 8, 256>>>(b1, W2);
    k_gather2<<<(NN + 7) / 8, 256>>>(b2, out);
}

// round 5
// speedup vs baseline: 1.3949x; 1.3949x over previous
#include <cuda_runtime.h>
#include <math.h>
#include <cstdint>

#define NN   100000
#define EE   1600000
#define FIN  512
#define HIDN 64
#define CO   16

#define SCAN_B 512
#define NBLK  ((NN + SCAN_B - 1) / SCAN_B)   // 196

// ---------------- scratch (device globals; no allocations allowed) ----------
__device__ int   g_degi[NN];
__device__ int   g_cnt [NN];
__device__ int   g_rs  [NN];
__device__ int   g_bsum [256];
__device__ int   g_bsumx[256];
__device__ float g_dis [NN];
__device__ int   g_esrc[EE];
__device__ float g_ew  [EE];
__device__ float g_h1  [(size_t)NN * HIDN];
__device__ float g_h2  [(size_t)NN * CO];
__device__ int   g_is64;

// ---------------- edge index dtype detection --------------------------------
__global__ void k_detect(const unsigned* __restrict__ w) {
    if (threadIdx.x == 0) {
        int is64 = 1;
        #pragma unroll 1
        for (int i = 1; i < 128; i += 2)
            if (w[i] != 0u) { is64 = 0; break; }
        g_is64 = is64;
    }
}

__device__ __forceinline__ int eidx(const void* edge, int is64, long long p) {
    return is64 ? (int)__ldg(((const long long*)edge) + p)
                : __ldg(((const int*)edge) + p);
}

// ---------------- per-launch init -------------------------------------------
__global__ void k_zero() {
    int i = blockIdx.x * blockDim.x + threadIdx.x;
    if (i < NN) { g_degi[i] = 0; g_cnt[i] = 0; }
}

__global__ void k_deg(const void* __restrict__ edge) {
    int e = blockIdx.x * blockDim.x + threadIdx.x;
    if (e >= EE) return;
    int dst = eidx(edge, g_is64, (long long)EE + e);
    atomicAdd(&g_degi[dst], 1);
}

__global__ void k_dis() {
    int i = blockIdx.x * blockDim.x + threadIdx.x;
    if (i < NN) g_dis[i] = rsqrtf((float)g_degi[i] + 1.0f);
}

// ---------------- exclusive scan of g_degi -> g_rs (2-level) ----------------
__global__ void k_scan1() {
    __shared__ int s[SCAN_B];
    int t = threadIdx.x, b = blockIdx.x, i = b * SCAN_B + t;
    int v = (i < NN) ? g_degi[i] : 0;
    s[t] = v; __syncthreads();
    for (int off = 1; off < SCAN_B; off <<= 1) {
        int xv = (t >= off) ? s[t - off] : 0;
        __syncthreads();
        s[t] += xv;
        __syncthreads();
    }
    if (i < NN) g_rs[i] = s[t] - v;
    if (t == SCAN_B - 1) g_bsum[b] = s[t];
}

__global__ void k_scan2() {
    __shared__ int s[256];
    int t = threadIdx.x;
    int v = (t < NBLK) ? g_bsum[t] : 0;
    s[t] = v; __syncthreads();
    for (int off = 1; off < 256; off <<= 1) {
        int xv = (t >= off) ? s[t - off] : 0;
        __syncthreads();
        s[t] += xv;
        __syncthreads();
    }
    g_bsumx[t] = s[t] - v;
}

__global__ void k_scan3() {
    int i = blockIdx.x * blockDim.x + threadIdx.x;
    if (i < NN) g_rs[i] += g_bsumx[i / SCAN_B];
}

// ---------------- counting-sort placement (CSR build) -----------------------
__global__ void k_build(const void* __restrict__ edge) {
    int e = blockIdx.x * blockDim.x + threadIdx.x;
    if (e >= EE) return;
    int is64 = g_is64;
    int src = eidx(edge, is64, e);
    int dst = eidx(edge, is64, (long long)EE + e);
    int pos = g_rs[dst] + atomicAdd(&g_cnt[dst], 1);
    g_esrc[pos] = src;
    g_ew[pos]   = g_dis[src] * g_dis[dst];
}

// ---------------- GEMM1 via mma.sync tf32: h1 = x @ W1 ----------------------
// Block tile 128(M) x 64(N), BK=32, 256 threads = 8 warps.
// Warp w owns n-slice [w*8, w*8+8) and iterates 8 m-tiles of 16 rows.
// mma.sync.aligned.m16n8k8.row.col.f32.tf32.tf32.f32
__device__ __forceinline__ uint32_t cvt_tf32(float f) {
    uint32_t r; asm("cvt.rna.tf32.f32 %0, %1;" : "=r"(r) : "f"(f)); return r;
}

#define APITCH 36   // floats; bank = (4*row + k) % 32 -> conflict-free frags

__global__ __launch_bounds__(256) void k_gemm1_mma(const float* __restrict__ x,
                                                   const float* __restrict__ W1) {
    __shared__ uint32_t As[128 * APITCH];   // [row][k], 18.4 KB
    __shared__ uint32_t Bs[HIDN * APITCH];  // [n][k],    9.2 KB

    int tid  = threadIdx.x;
    int wid  = tid >> 5, lane = tid & 31;
    int rg   = lane >> 2;        // group id (row within 16-tile / n within 8)
    int tg   = lane & 3;         // thread in group (k)
    int rowBase = blockIdx.x * 128;

    float d[8][4];
    #pragma unroll
    for (int m = 0; m < 8; m++)
        #pragma unroll
        for (int q = 0; q < 4; q++) d[m][q] = 0.0f;

    for (int k0 = 0; k0 < FIN; k0 += 32) {
        // stage A: 128 rows x 32 k (4 float4 per thread)
        #pragma unroll
        for (int l = 0; l < 4; l++) {
            int idx = tid + l * 256;
            int r = idx >> 3, c8 = idx & 7;
            int gr = rowBase + r;
            float4 v = make_float4(0.f, 0.f, 0.f, 0.f);
            if (gr < NN) v = *(const float4*)&x[(size_t)gr * FIN + k0 + c8 * 4];
            uint32_t* p = &As[r * APITCH + c8 * 4];
            p[0] = cvt_tf32(v.x); p[1] = cvt_tf32(v.y);
            p[2] = cvt_tf32(v.z); p[3] = cvt_tf32(v.w);
        }
        // stage B transposed: Bs[n][kk] = W1[(k0+kk)*64 + n]
        #pragma unroll
        for (int l = 0; l < 8; l++) {
            int idx = tid + l * 256;
            int kk = idx >> 6, n = idx & 63;
            Bs[n * APITCH + kk] = cvt_tf32(W1[(k0 + kk) * HIDN + n]);
        }
        __syncthreads();

        #pragma unroll
        for (int k8 = 0; k8 < 4; k8++) {
            int kb = k8 * 8 + tg;
            // B fragment (n-slice = wid*8)
            uint32_t b0 = Bs[(wid * 8 + rg) * APITCH + kb];
            uint32_t b1 = Bs[(wid * 8 + rg) * APITCH + kb + 4];
            #pragma unroll
            for (int m = 0; m < 8; m++) {
                int r0 = m * 16 + rg;
                uint32_t a0 = As[(r0    ) * APITCH + kb];
                uint32_t a1 = As[(r0 + 8) * APITCH + kb];
                uint32_t a2 = As[(r0    ) * APITCH + kb + 4];
                uint32_t a3 = As[(r0 + 8) * APITCH + kb + 4];
                asm volatile(
                    "mma.sync.aligned.m16n8k8.row.col.f32.tf32.tf32.f32 "
                    "{%0,%1,%2,%3}, {%4,%5,%6,%7}, {%8,%9}, {%0,%1,%2,%3};"
                    : "+f"(d[m][0]), "+f"(d[m][1]), "+f"(d[m][2]), "+f"(d[m][3])
                    : "r"(a0), "r"(a1), "r"(a2), "r"(a3), "r"(b0), "r"(b1));
            }
        }
        __syncthreads();
    }

    // write-out: d[m][0,1] -> (row rg, cols 2tg,2tg+1); d[m][2,3] -> row rg+8
    int colBase = wid * 8 + tg * 2;
    #pragma unroll
    for (int m = 0; m < 8; m++) {
        int r0 = rowBase + m * 16 + rg;
        if (r0 < NN)
            *(float2*)&g_h1[(size_t)r0 * HIDN + colBase] =
                make_float2(d[m][0], d[m][1]);
        int r1 = r0 + 8;
        if (r1 < NN)
            *(float2*)&g_h1[(size_t)r1 * HIDN + colBase] =
                make_float2(d[m][2], d[m][3]);
    }
}

// ---------------- gather layer 1 (fused relu + bias + self-loop + GEMM2) ----
__global__ __launch_bounds__(256) void k_gather1(const float* __restrict__ b1,
                                                 const float* __restrict__ W2) {
    __shared__ float W2s[HIDN * CO];
    __shared__ float b1s[HIDN];
    __shared__ float hs[8][HIDN];
    for (int i = threadIdx.x; i < HIDN * CO; i += 256) W2s[i] = W2[i];
    if (threadIdx.x < HIDN) b1s[threadIdx.x] = b1[threadIdx.x];
    __syncthreads();

    int warp = threadIdx.x >> 5, lane = threadIdx.x & 31;
    int n = blockIdx.x * 8 + warp;
    if (n >= NN) return;

    float acc0 = 0.0f, acc1 = 0.0f;
    int beg = g_rs[n], end = beg + g_degi[n];

    int e = beg;
    for (; e + 1 < end; e += 2) {
        int   s0 = g_esrc[e],   s1 = g_esrc[e + 1];
        float w0 = g_ew[e],     w1 = g_ew[e + 1];
        float2 v0 = *(const float2*)&g_h1[(size_t)s0 * HIDN + lane * 2];
        float2 v1 = *(const float2*)&g_h1[(size_t)s1 * HIDN + lane * 2];
        acc0 += w0 * v0.x + w1 * v1.x;
        acc1 += w0 * v0.y + w1 * v1.y;
    }
    if (e < end) {
        int s0 = g_esrc[e]; float w0 = g_ew[e];
        float2 v0 = *(const float2*)&g_h1[(size_t)s0 * HIDN + lane * 2];
        acc0 += w0 * v0.x;
        acc1 += w0 * v0.y;
    }

    float dd = g_dis[n]; dd *= dd;
    float2 hv = *(const float2*)&g_h1[(size_t)n * HIDN + lane * 2];
    acc0 = fmaxf(acc0 + dd * hv.x + b1s[lane * 2 + 0], 0.0f);
    acc1 = fmaxf(acc1 + dd * hv.y + b1s[lane * 2 + 1], 0.0f);
    hs[warp][lane * 2 + 0] = acc0;
    hs[warp][lane * 2 + 1] = acc1;
    __syncwarp();

    int c = lane & 15, half = lane >> 4;
    float s = 0.0f;
    #pragma unroll
    for (int k = half * 32; k < half * 32 + 32; k++)
        s += hs[warp][k] * W2s[k * CO + c];
    s += __shfl_down_sync(0xffffffffu, s, 16);
    if (half == 0) g_h2[(size_t)n * CO + c] = s;
}

// ---------------- gather layer 2 (fused bias + self-loop + log_softmax) -----
__global__ __launch_bounds__(256) void k_gather2(const float* __restrict__ b2,
                                                 float* __restrict__ out) {
    int warp = threadIdx.x >> 5, lane = threadIdx.x & 31;
    int n = blockIdx.x * 8 + warp;
    if (n >= NN) return;
    int c = lane & 15, half = lane >> 4;

    float acc = 0.0f;
    int beg = g_rs[n], end = beg + g_degi[n];
    for (int e = beg + half; e < end; e += 2)
        acc += g_ew[e] * g_h2[(size_t)g_esrc[e] * CO + c];
    acc += __shfl_xor_sync(0xffffffffu, acc, 16);

    float dd = g_dis[n]; dd *= dd;
    float z = acc + dd * g_h2[(size_t)n * CO + c] + __ldg(&b2[c]);

    float m = z;
    #pragma unroll
    for (int off = 8; off; off >>= 1)
        m = fmaxf(m, __shfl_xor_sync(0xffffffffu, m, off));
    float sum = expf(z - m);
    #pragma unroll
    for (int off = 8; off; off >>= 1)
        sum += __shfl_xor_sync(0xffffffffu, sum, off);
    float l = m + logf(sum);

    if (half == 0) out[(size_t)n * CO + c] = z - l;
}

// ---------------- launch -----------------------------------------------------
extern "C" void kernel_launch(void* const* d_in, const int* in_sizes, int n_in,
                              void* d_out, int out_size) {
    const float* x    = (const float*)d_in[0];
    const void*  edge = d_in[1];
    const float* W1   = (const float*)d_in[2];
    const float* b1   = (const float*)d_in[3];
    const float* W2   = (const float*)d_in[4];
    const float* b2   = (const float*)d_in[5];
    float* out = (float*)d_out;

    k_detect<<<1, 32>>>((const unsigned*)edge);
    k_zero<<<(NN + 255) / 256, 256>>>();
    k_deg<<<(EE + 255) / 256, 256>>>(edge);
    k_dis<<<(NN + 255) / 256, 256>>>();
    k_scan1<<<NBLK, SCAN_B>>>();
    k_scan2<<<1, 256>>>();
    k_scan3<<<(NN + 255) / 256, 256>>>();
    k_build<<<(EE + 255) / 256, 256>>>(edge);
    k_gemm1_mma<<<(NN + 127) / 128, 256>>>(x, W1);
    k_gather1<<<(NN + 7) / 8, 256>>>(b1, W2);
    k_gather2<<<(NN + 7) / 8, 256>>>(b2, out);
}

// round 9
// speedup vs baseline: 1.4255x; 1.0220x over previous
#include <cuda_runtime.h>
#include <math.h>
#include <cstdint>

#define NN   100000
#define EE   1600000
#define FIN  512
#define HIDN 64
#define CO   16

#define SCAN_B 512
#define NBLK  ((NN + SCAN_B - 1) / SCAN_B)   // 196

// ---------------- scratch (device globals; no allocations allowed) ----------
__device__ int   g_degi[NN];
__device__ int   g_cnt [NN];
__device__ int   g_rs  [NN];
__device__ int   g_bsum [256];
__device__ int   g_bsumx[256];
__device__ float g_dis [NN];
__device__ int   g_esrc[EE];
__device__ float g_ew  [EE];
__device__ float g_h1  [(size_t)NN * HIDN];
__device__ float g_h2  [(size_t)NN * CO];
__device__ int   g_is64;

__device__ __forceinline__ int eidx(const void* edge, int is64, long long p) {
    return is64 ? (int)__ldg(((const long long*)edge) + p)
                : __ldg(((const int*)edge) + p);
}

// ---------------- init: zero counters + edge dtype detection ----------------
__global__ void k_zero(const unsigned* __restrict__ w) {
    int i = blockIdx.x * blockDim.x + threadIdx.x;
    if (i < NN) { g_degi[i] = 0; g_cnt[i] = 0; }
    if (i == 0) {
        // int64 storage => high word of each entry is 0 (indices < 100000).
        int is64 = 1;
        #pragma unroll 1
        for (int j = 1; j < 128; j += 2)
            if (w[j] != 0u) { is64 = 0; break; }
        g_is64 = is64;
    }
}

__global__ void k_deg(const void* __restrict__ edge) {
    int e = blockIdx.x * blockDim.x + threadIdx.x;
    if (e >= EE) return;
    int dst = eidx(edge, g_is64, (long long)EE + e);
    atomicAdd(&g_degi[dst], 1);
}

// ---------------- exclusive scan of g_degi -> g_rs + fused dis --------------
__global__ void k_scan1() {
    __shared__ int s[SCAN_B];
    int t = threadIdx.x, b = blockIdx.x, i = b * SCAN_B + t;
    int v = (i < NN) ? g_degi[i] : 0;
    if (i < NN) g_dis[i] = rsqrtf((float)v + 1.0f);   // fused k_dis
    s[t] = v; __syncthreads();
    for (int off = 1; off < SCAN_B; off <<= 1) {
        int xv = (t >= off) ? s[t - off] : 0;
        __syncthreads();
        s[t] += xv;
        __syncthreads();
    }
    if (i < NN) g_rs[i] = s[t] - v;
    if (t == SCAN_B - 1) g_bsum[b] = s[t];
}

__global__ void k_scan2() {
    __shared__ int s[256];
    int t = threadIdx.x;
    int v = (t < NBLK) ? g_bsum[t] : 0;
    s[t] = v; __syncthreads();
    for (int off = 1; off < 256; off <<= 1) {
        int xv = (t >= off) ? s[t - off] : 0;
        __syncthreads();
        s[t] += xv;
        __syncthreads();
    }
    g_bsumx[t] = s[t] - v;
}

__global__ void k_scan3() {
    int i = blockIdx.x * blockDim.x + threadIdx.x;
    if (i < NN) g_rs[i] += g_bsumx[i / SCAN_B];
}

// ---------------- counting-sort placement (CSR build) -----------------------
__global__ void k_build(const void* __restrict__ edge) {
    int e = blockIdx.x * blockDim.x + threadIdx.x;
    if (e >= EE) return;
    int is64 = g_is64;
    int src = eidx(edge, is64, e);
    int dst = eidx(edge, is64, (long long)EE + e);
    int pos = g_rs[dst] + atomicAdd(&g_cnt[dst], 1);
    g_esrc[pos] = src;
    g_ew[pos]   = g_dis[src] * g_dis[dst];
}

// ---------------- GEMM1 via mma.sync tf32: h1 = x @ W1 ----------------------
__device__ __forceinline__ uint32_t cvt_tf32(float f) {
    uint32_t r; asm("cvt.rna.tf32.f32 %0, %1;" : "=r"(r) : "f"(f)); return r;
}

#define APITCH 36

__global__ __launch_bounds__(256) void k_gemm1_mma(const float* __restrict__ x,
                                                   const float* __restrict__ W1) {
    __shared__ uint32_t As[128 * APITCH];
    __shared__ uint32_t Bs[HIDN * APITCH];

    int tid  = threadIdx.x;
    int wid  = tid >> 5, lane = tid & 31;
    int rg   = lane >> 2;
    int tg   = lane & 3;
    int rowBase = blockIdx.x * 128;

    float d[8][4];
    #pragma unroll
    for (int m = 0; m < 8; m++)
        #pragma unroll
        for (int q = 0; q < 4; q++) d[m][q] = 0.0f;

    for (int k0 = 0; k0 < FIN; k0 += 32) {
        #pragma unroll
        for (int l = 0; l < 4; l++) {
            int idx = tid + l * 256;
            int r = idx >> 3, c8 = idx & 7;
            int gr = rowBase + r;
            float4 v = make_float4(0.f, 0.f, 0.f, 0.f);
            if (gr < NN) v = *(const float4*)&x[(size_t)gr * FIN + k0 + c8 * 4];
            uint32_t* p = &As[r * APITCH + c8 * 4];
            p[0] = cvt_tf32(v.x); p[1] = cvt_tf32(v.y);
            p[2] = cvt_tf32(v.z); p[3] = cvt_tf32(v.w);
        }
        #pragma unroll
        for (int l = 0; l < 8; l++) {
            int idx = tid + l * 256;
            int kk = idx >> 6, n = idx & 63;
            Bs[n * APITCH + kk] = cvt_tf32(W1[(k0 + kk) * HIDN + n]);
        }
        __syncthreads();

        #pragma unroll
        for (int k8 = 0; k8 < 4; k8++) {
            int kb = k8 * 8 + tg;
            uint32_t b0 = Bs[(wid * 8 + rg) * APITCH + kb];
            uint32_t b1 = Bs[(wid * 8 + rg) * APITCH + kb + 4];
            #pragma unroll
            for (int m = 0; m < 8; m++) {
                int r0 = m * 16 + rg;
                uint32_t a0 = As[(r0    ) * APITCH + kb];
                uint32_t a1 = As[(r0 + 8) * APITCH + kb];
                uint32_t a2 = As[(r0    ) * APITCH + kb + 4];
                uint32_t a3 = As[(r0 + 8) * APITCH + kb + 4];
                asm volatile(
                    "mma.sync.aligned.m16n8k8.row.col.f32.tf32.tf32.f32 "
                    "{%0,%1,%2,%3}, {%4,%5,%6,%7}, {%8,%9}, {%0,%1,%2,%3};"
                    : "+f"(d[m][0]), "+f"(d[m][1]), "+f"(d[m][2]), "+f"(d[m][3])
                    : "r"(a0), "r"(a1), "r"(a2), "r"(a3), "r"(b0), "r"(b1));
            }
        }
        __syncthreads();
    }

    int colBase = wid * 8 + tg * 2;
    #pragma unroll
    for (int m = 0; m < 8; m++) {
        int r0 = rowBase + m * 16 + rg;
        if (r0 < NN)
            *(float2*)&g_h1[(size_t)r0 * HIDN + colBase] =
                make_float2(d[m][0], d[m][1]);
        int r1 = r0 + 8;
        if (r1 < NN)
            *(float2*)&g_h1[(size_t)r1 * HIDN + colBase] =
                make_float2(d[m][2], d[m][3]);
    }
}

// ---------------- gather layer 1 (fused relu + bias + self-loop + GEMM2) ----
__global__ __launch_bounds__(256) void k_gather1(const float* __restrict__ b1,
                                                 const float* __restrict__ W2) {
    __shared__ float W2s[HIDN * CO];
    __shared__ float b1s[HIDN];
    __shared__ float hs[8][HIDN];
    for (int i = threadIdx.x; i < HIDN * CO; i += 256) W2s[i] = W2[i];
    if (threadIdx.x < HIDN) b1s[threadIdx.x] = b1[threadIdx.x];
    __syncthreads();

    int warp = threadIdx.x >> 5, lane = threadIdx.x & 31;
    int n = blockIdx.x * 8 + warp;
    if (n >= NN) return;

    float acc0 = 0.0f, acc1 = 0.0f;
    int beg = g_rs[n], end = beg + g_degi[n];

    int e = beg;
    for (; e + 3 < end; e += 4) {
        int   s0 = g_esrc[e],     s1 = g_esrc[e + 1];
        int   s2 = g_esrc[e + 2], s3 = g_esrc[e + 3];
        float w0 = g_ew[e],       w1 = g_ew[e + 1];
        float w2 = g_ew[e + 2],   w3 = g_ew[e + 3];
        float2 v0 = *(const float2*)&g_h1[(size_t)s0 * HIDN + lane * 2];
        float2 v1 = *(const float2*)&g_h1[(size_t)s1 * HIDN + lane * 2];
        float2 v2 = *(const float2*)&g_h1[(size_t)s2 * HIDN + lane * 2];
        float2 v3 = *(const float2*)&g_h1[(size_t)s3 * HIDN + lane * 2];
        acc0 += w0 * v0.x + w1 * v1.x + w2 * v2.x + w3 * v3.x;
        acc1 += w0 * v0.y + w1 * v1.y + w2 * v2.y + w3 * v3.y;
    }
    for (; e < end; e++) {
        int s0 = g_esrc[e]; float w0 = g_ew[e];
        float2 v0 = *(const float2*)&g_h1[(size_t)s0 * HIDN + lane * 2];
        acc0 += w0 * v0.x;
        acc1 += w0 * v0.y;
    }

    float dd = g_dis[n]; dd *= dd;
    float2 hv = *(const float2*)&g_h1[(size_t)n * HIDN + lane * 2];
    acc0 = fmaxf(acc0 + dd * hv.x + b1s[lane * 2 + 0], 0.0f);
    acc1 = fmaxf(acc1 + dd * hv.y + b1s[lane * 2 + 1], 0.0f);
    hs[warp][lane * 2 + 0] = acc0;
    hs[warp][lane * 2 + 1] = acc1;
    __syncwarp();

    int c = lane & 15, half = lane >> 4;
    float s = 0.0f;
    #pragma unroll
    for (int k = half * 32; k < half * 32 + 32; k++)
        s += hs[warp][k] * W2s[k * CO + c];
    s += __shfl_down_sync(0xffffffffu, s, 16);
    if (half == 0) g_h2[(size_t)n * CO + c] = s;
}

// ---------------- gather layer 2 (fused bias + self-loop + log_softmax) -----
__global__ __launch_bounds__(256) void k_gather2(const float* __restrict__ b2,
                                                 float* __restrict__ out) {
    int warp = threadIdx.x >> 5, lane = threadIdx.x & 31;
    int n = blockIdx.x * 8 + warp;
    if (n >= NN) return;
    int c = lane & 15, half = lane >> 4;

    float acc = 0.0f;
    int beg = g_rs[n], end = beg + g_degi[n];
    for (int e = beg + half; e < end; e += 2)
        acc += g_ew[e] * g_h2[(size_t)g_esrc[e] * CO + c];
    acc += __shfl_xor_sync(0xffffffffu, acc, 16);

    float dd = g_dis[n]; dd *= dd;
    float z = acc + dd * g_h2[(size_t)n * CO + c] + __ldg(&b2[c]);

    float m = z;
    #pragma unroll
    for (int off = 8; off; off >>= 1)
        m = fmaxf(m, __shfl_xor_sync(0xffffffffu, m, off));
    float sum = expf(z - m);
    #pragma unroll
    for (int off = 8; off; off >>= 1)
        sum += __shfl_xor_sync(0xffffffffu, sum, off);
    float l = m + logf(sum);

    if (half == 0) out[(size_t)n * CO + c] = z - l;
}

// ---------------- launch -----------------------------------------------------
extern "C" void kernel_launch(void* const* d_in, const int* in_sizes, int n_in,
                              void* d_out, int out_size) {
    const float* x    = (const float*)d_in[0];
    const void*  edge = d_in[1];
    const float* W1   = (const float*)d_in[2];
    const float* b1   = (const float*)d_in[3];
    const float* W2   = (const float*)d_in[4];
    const float* b2   = (const float*)d_in[5];
    float* out = (float*)d_out;

    k_zero<<<(NN + 255) / 256, 256>>>((const unsigned*)edge);
    k_deg<<<(EE + 255) / 256, 256>>>(edge);
    k_scan1<<<NBLK, SCAN_B>>>();
    k_scan2<<<1, 256>>>();
    k_scan3<<<(NN + 255) / 256, 256>>>();
    k_build<<<(EE + 255) / 256, 256>>>(edge);
    k_gemm1_mma<<<(NN + 127) / 128, 256>>>(x, W1);
    k_gather1<<<(NN + 7) / 8, 256>>>(b1, W2);
    k_gather2<<<(NN + 7) / 8, 256>>>(b2, out);
}